// round 13
// baseline (speedup 1.0000x reference)
#include <cuda_runtime.h>
#include <cuda_bf16.h>
#include <math.h>
#include <cstdint>

// Problem constants: B=2, N=8192, DIM=512, H=8, A=256, D=64
__device__ float g_kv [16 * 256 * 64];       // fused num -> normalized kv
__device__ float g_ksum[16 * 256];           // softmax denominators
__device__ float g_tsum;
// bf16 hi/lo split buffers (k1 inputs)
__device__ __align__(16) __nv_bfloat16 g_xh[16384 * 512];
__device__ __align__(16) __nv_bfloat16 g_xl[16384 * 512];
__device__ __align__(16) __nv_bfloat16 g_wh[1536 * 512];
__device__ __align__(16) __nv_bfloat16 g_wl[1536 * 512];
__device__ __align__(16) __nv_bfloat16 g_agh[8 * 256 * 64];
__device__ __align__(16) __nv_bfloat16 g_agl[8 * 256 * 64];
// q/k/v presplit head-major [bh][n][64] (q pre-scaled by 0.125)
__device__ __align__(16) __nv_bfloat16 g_qh[16 * 8192 * 64];
__device__ __align__(16) __nv_bfloat16 g_ql[16 * 8192 * 64];
__device__ __align__(16) __nv_bfloat16 g_kh[16 * 8192 * 64];
__device__ __align__(16) __nv_bfloat16 g_kl[16 * 8192 * 64];
__device__ __align__(16) __nv_bfloat16 g_vh[16 * 8192 * 64];
__device__ __align__(16) __nv_bfloat16 g_vl[16 * 8192 * 64];
// kv2 transposed [bh][d][a], bf16 hi/lo
__device__ __align__(16) __nv_bfloat16 g_kt_h[16 * 64 * 256];
__device__ __align__(16) __nv_bfloat16 g_kt_l[16 * 64 * 256];

// ===========================================================================
// PTX helpers
// ===========================================================================
__device__ __forceinline__ uint32_t smem_to_u32(const void* p) {
    uint32_t a;
    asm("{ .reg .u64 t; cvta.to.shared.u64 t, %1; cvt.u32.u64 %0, t; }" : "=r"(a) : "l"(p));
    return a;
}
#define LDMATRIX_X4(r0, r1, r2, r3, addr) \
    asm volatile("ldmatrix.sync.aligned.m8n8.x4.shared.b16 {%0,%1,%2,%3}, [%4];" \
                 : "=r"(r0), "=r"(r1), "=r"(r2), "=r"(r3) : "r"(addr))
#define LDMATRIX_X4_T(r0, r1, r2, r3, addr) \
    asm volatile("ldmatrix.sync.aligned.m8n8.x4.trans.shared.b16 {%0,%1,%2,%3}, [%4];" \
                 : "=r"(r0), "=r"(r1), "=r"(r2), "=r"(r3) : "r"(addr))
#define MMA_BF16(c, a, b) \
    asm volatile("mma.sync.aligned.m16n8k16.row.col.f32.bf16.bf16.f32 " \
                 "{%0,%1,%2,%3}, {%4,%5,%6,%7}, {%8,%9}, {%0,%1,%2,%3};" \
                 : "+f"((c)[0]), "+f"((c)[1]), "+f"((c)[2]), "+f"((c)[3]) \
                 : "r"((a)[0]), "r"((a)[1]), "r"((a)[2]), "r"((a)[3]), \
                   "r"((b)[0]), "r"((b)[1]))
#define CP_ASYNC16(dst, src) \
    asm volatile("cp.async.cg.shared.global [%0], [%1], 16;" :: "r"(dst), "l"(src))
#define CP_COMMIT() asm volatile("cp.async.commit_group;" ::: "memory")
#define CP_WAIT0()  asm volatile("cp.async.wait_group 0;" ::: "memory")
#define CP_WAIT1()  asm volatile("cp.async.wait_group 1;" ::: "memory")

// pack two floats -> bf16x2 hi word and residual lo word
__device__ __forceinline__ void split2(float a, float b, uint32_t& h, uint32_t& l) {
    __nv_bfloat16 ha = __float2bfloat16_rn(a), hb = __float2bfloat16_rn(b);
    __nv_bfloat162 hp; hp.x = ha; hp.y = hb;
    __nv_bfloat162 lp;
    lp.x = __float2bfloat16_rn(a - __bfloat162float(ha));
    lp.y = __float2bfloat16_rn(b - __bfloat162float(hb));
    h = *(uint32_t*)&hp; l = *(uint32_t*)&lp;
}

// ===========================================================================
// bf16 split kernel (x, w_qkv, agent)
// ===========================================================================
__global__ __launch_bounds__(256)
void split_bf16(const float* __restrict__ in, __nv_bfloat16* __restrict__ hi,
                __nv_bfloat16* __restrict__ lo, long n) {
    for (long i = ((long)blockIdx.x * blockDim.x + threadIdx.x) * 4; i < n;
         i += (long)gridDim.x * blockDim.x * 4) {
        float4 v = *(const float4*)(in + i);
        uint32_t h01, h23, l01, l23;
        split2(v.x, v.y, h01, l01);
        split2(v.z, v.w, h23, l23);
        *(uint2*)(hi + i) = make_uint2(h01, h23);
        *(uint2*)(lo + i) = make_uint2(l01, l23);
    }
}

// ===========================================================================
// K1: [16384,1536] = X @ W^T via bf16x3 mma.sync (verified 8-warp config).
// Epilogue writes q (x0.125) / k / v directly as bf16 hi/lo, head-major.
// ===========================================================================
static constexpr int K1_ROWB = 80;
static constexpr int K1_BUF  = 128 * K1_ROWB;
static constexpr int K1_STAGE = 4 * K1_BUF;
static constexpr int K1_SMEM  = 2 * K1_STAGE;

__global__ __launch_bounds__(256)
void k1_mma_kernel(const __nv_bfloat16* __restrict__ xh,
                   const __nv_bfloat16* __restrict__ xl,
                   const __nv_bfloat16* __restrict__ wh,
                   const __nv_bfloat16* __restrict__ wl,
                   __nv_bfloat16* __restrict__ qh, __nv_bfloat16* __restrict__ ql,
                   __nv_bfloat16* __restrict__ kh, __nv_bfloat16* __restrict__ kl,
                   __nv_bfloat16* __restrict__ vh, __nv_bfloat16* __restrict__ vl)
{
    extern __shared__ char smem[];
    uint32_t sb = smem_to_u32(smem);
    int tid = threadIdx.x;
    int lane = tid & 31, wid = tid >> 5;
    int mw = wid & 1, nw = wid >> 1;          // warp grid 2m x 4n
    int nt = blockIdx.x, mt = blockIdx.y;

    const __nv_bfloat16* srcA_h = xh + (long)(mt * 128) * 512;
    const __nv_bfloat16* srcA_l = xl + (long)(mt * 128) * 512;
    const __nv_bfloat16* srcB_h = wh + (long)(nt * 128) * 512;
    const __nv_bfloat16* srcB_l = wl + (long)(nt * 128) * 512;

    float acc[4][4][4];
#pragma unroll
    for (int i = 0; i < 4; i++)
#pragma unroll
        for (int j = 0; j < 4; j++)
#pragma unroll
            for (int q = 0; q < 4; q++) acc[i][j][q] = 0.f;

    int a_tile = lane >> 3, a_rin = lane & 7;
    int a_row = a_rin + (a_tile & 1) * 8;
    int a_kb  = (a_tile >> 1) * 16;
    int b_row = (a_tile >> 1) * 8 + a_rin;
    int b_kb  = (a_tile & 1) * 16;

    auto issue_loads = [&](int stage, int k0) {
        uint32_t base = sb + stage * K1_STAGE;
#pragma unroll
        for (int j = 0; j < 8; j++) {
            int idx = tid + j * 256;
            int buf = idx >> 9;
            int r   = (idx >> 2) & 127;
            int g   = idx & 3;
            const __nv_bfloat16* src =
                (buf == 0 ? srcA_h : buf == 1 ? srcA_l : buf == 2 ? srcB_h : srcB_l)
                + (long)r * 512 + k0 + g * 8;
            uint32_t dst = base + buf * K1_BUF + r * K1_ROWB + g * 16;
            CP_ASYNC16(dst, src);
        }
    };

    issue_loads(0, 0);
    CP_COMMIT(); CP_WAIT0();
    __syncthreads();

    for (int kc = 0; kc < 16; ++kc) {
        int cur = kc & 1;
        if (kc < 15) { issue_loads(cur ^ 1, (kc + 1) * 32); CP_COMMIT(); }

        uint32_t st = sb + cur * K1_STAGE;
        uint32_t Ah = st,              Al = st + K1_BUF;
        uint32_t Bh = st + 2 * K1_BUF, Bl = st + 3 * K1_BUF;

#pragma unroll
        for (int s = 0; s < 2; ++s) {
            int skb = s * 32;
            uint32_t ah[4][4], al[4][4], bh[4][2], bl[4][2];
#pragma unroll
            for (int mf = 0; mf < 4; mf++) {
                uint32_t addr = Ah + (mw * 64 + mf * 16 + a_row) * K1_ROWB + skb + a_kb;
                LDMATRIX_X4(ah[mf][0], ah[mf][1], ah[mf][2], ah[mf][3], addr);
            }
#pragma unroll
            for (int p = 0; p < 2; p++) {
                uint32_t addr = Bh + (nw * 32 + p * 16 + b_row) * K1_ROWB + skb + b_kb;
                LDMATRIX_X4(bh[p * 2][0], bh[p * 2][1], bh[p * 2 + 1][0], bh[p * 2 + 1][1], addr);
                uint32_t addr2 = Bl + (nw * 32 + p * 16 + b_row) * K1_ROWB + skb + b_kb;
                LDMATRIX_X4(bl[p * 2][0], bl[p * 2][1], bl[p * 2 + 1][0], bl[p * 2 + 1][1], addr2);
            }
#pragma unroll
            for (int mf = 0; mf < 4; mf++)
#pragma unroll
                for (int nf = 0; nf < 4; nf++) MMA_BF16(acc[mf][nf], ah[mf], bh[nf]);
#pragma unroll
            for (int mf = 0; mf < 4; mf++)
#pragma unroll
                for (int nf = 0; nf < 4; nf++) MMA_BF16(acc[mf][nf], ah[mf], bl[nf]);
#pragma unroll
            for (int mf = 0; mf < 4; mf++) {
                uint32_t addr = Al + (mw * 64 + mf * 16 + a_row) * K1_ROWB + skb + a_kb;
                LDMATRIX_X4(al[mf][0], al[mf][1], al[mf][2], al[mf][3], addr);
            }
#pragma unroll
            for (int mf = 0; mf < 4; mf++)
#pragma unroll
                for (int nf = 0; nf < 4; nf++) MMA_BF16(acc[mf][nf], al[mf], bh[nf]);
        }

        if (kc < 15) CP_WAIT0();
        __syncthreads();
    }

    // Epilogue: split-write to per-head hi/lo arrays. nt tile (128 cols) lies
    // fully within one part (512-col) since 512 % 128 == 0.
    int part = nt >> 2;
    const float scp = (part == 0) ? 0.125f : 1.f;
    __nv_bfloat16* hdst = part == 0 ? qh : (part == 1 ? kh : vh);
    __nv_bfloat16* ldst = part == 0 ? ql : (part == 1 ? kl : vl);
    int rbase = mt * 128 + mw * 64 + (lane >> 2);
    int b = rbase >> 13;
    int nn = rbase & 8191;
    int cbase = nt * 128 + nw * 32 + (lane & 3) * 2;
#pragma unroll
    for (int mf = 0; mf < 4; mf++)
#pragma unroll
        for (int nf = 0; nf < 4; nf++) {
            int cc = cbase + nf * 8;
            int h = (cc >> 6) & 7;
            int d = cc & 63;
            long base = ((long)((b << 3) | h) * 8192 + nn + mf * 16) * 64 + d;
            uint32_t hw, lw;
            split2(acc[mf][nf][0] * scp, acc[mf][nf][1] * scp, hw, lw);
            *(uint32_t*)(hdst + base) = hw; *(uint32_t*)(ldst + base) = lw;
            split2(acc[mf][nf][2] * scp, acc[mf][nf][3] * scp, hw, lw);
            *(uint32_t*)(hdst + base + 512) = hw; *(uint32_t*)(ldst + base + 512) = lw;
        }
}

// ===========================================================================
// init: zero atomic accumulators
// ===========================================================================
__global__ void init_kernel() {
    int i = blockIdx.x * blockDim.x + threadIdx.x;
    if (i == 0) g_tsum = 0.f;
    if (i < 16 * 256) g_ksum[i] = 0.f;
    for (; i < 16 * 256 * 64; i += gridDim.x * blockDim.x) g_kv[i] = 0.f;
}

// ===========================================================================
// Fused stage A: S = agent@K^T, P = exp, num += P@V, den += rowsum.
// Pre-split K/V via cp.async, 2-stage pipeline. grid (16,16), 256 threads.
// ===========================================================================
static constexpr int A_STR    = 144;
static constexpr int A_AGL    = 36864;
static constexpr int A_T      = 73728;        // tile stages base
static constexpr int A_TSTAGE = 18432;        // KH/KL/VH/VL 4608 each
static constexpr int A_SMEM   = 110592;

__global__ __launch_bounds__(256)
void attn_kv_kernel(const __nv_bfloat16* __restrict__ kh,
                    const __nv_bfloat16* __restrict__ kl,
                    const __nv_bfloat16* __restrict__ vh,
                    const __nv_bfloat16* __restrict__ vl,
                    const __nv_bfloat16* __restrict__ agh,
                    const __nv_bfloat16* __restrict__ agl,
                    float* __restrict__ kv, float* __restrict__ ksum)
{
    extern __shared__ char smem[];
    uint32_t sb = smem_to_u32(smem);
    int tid = threadIdx.x, lane = tid & 31, wid = tid >> 5;
    int split = blockIdx.x, bh = blockIdx.y;
    int h = bh & 7;
    int t8 = lane >> 3, rin = lane & 7;
    int a_row = rin + (t8 & 1) * 8, a_kb = (t8 >> 1) * 16;
    int b_row = (t8 >> 1) * 8 + rin, b_kb = (t8 & 1) * 16;
    int v_row = (t8 & 1) * 8 + rin, v_cb = (t8 >> 1) * 16;

    long tok0 = (long)bh * 8192 * 64 + (long)(split * 512) * 64;

    auto issue_tile = [&](int t) {
        uint32_t st = sb + A_T + (t & 1) * A_TSTAGE;
        long tb = tok0 + (long)t * 32 * 64;
#pragma unroll
        for (int j = 0; j < 4; j++) {
            int idx = tid + j * 256;
            int arr = idx >> 8;
            int r = (idx >> 3) & 31;
            int c = idx & 7;
            const __nv_bfloat16* src =
                (arr == 0 ? kh : arr == 1 ? kl : arr == 2 ? vh : vl) + tb + r * 64 + c * 8;
            CP_ASYNC16(st + arr * 4608 + r * A_STR + c * 16, src);
        }
    };

    // prologue: agent + tile0 (one group)
    {
        const __nv_bfloat16* ah_p = agh + h * 16384;
        const __nv_bfloat16* al_p = agl + h * 16384;
        for (int i = tid; i < 2048; i += 256) {
            int r = i >> 3, c = i & 7;
            CP_ASYNC16(sb + r * A_STR + c * 16,         ah_p + r * 64 + c * 8);
            CP_ASYNC16(sb + A_AGL + r * A_STR + c * 16, al_p + r * 64 + c * 8);
        }
        issue_tile(0);
        CP_COMMIT();
    }

    float kvacc[2][8][4];
#pragma unroll
    for (int i = 0; i < 2; i++)
#pragma unroll
        for (int j = 0; j < 8; j++)
#pragma unroll
            for (int q = 0; q < 4; q++) kvacc[i][j][q] = 0.f;
    float rs[2][2] = {{0.f, 0.f}, {0.f, 0.f}};

    for (int t = 0; t < 16; ++t) {
        if (t < 15) { issue_tile(t + 1); CP_COMMIT(); CP_WAIT1(); }
        else        { CP_WAIT0(); }
        __syncthreads();

        uint32_t st = sb + A_T + (t & 1) * A_TSTAGE;
        uint32_t KH = st, KL = st + 4608, VH = st + 9216, VL = st + 13824;

        float s[2][4][4];
#pragma unroll
        for (int i = 0; i < 2; i++)
#pragma unroll
            for (int j = 0; j < 4; j++)
#pragma unroll
                for (int q = 0; q < 4; q++) s[i][j][q] = 0.f;

#pragma unroll
        for (int kf = 0; kf < 4; ++kf) {
            uint32_t ah[2][4], al[2][4];
#pragma unroll
            for (int mf = 0; mf < 2; ++mf) {
                uint32_t ad = sb + (wid * 32 + mf * 16 + a_row) * A_STR + kf * 32 + a_kb;
                LDMATRIX_X4(ah[mf][0], ah[mf][1], ah[mf][2], ah[mf][3], ad);
                LDMATRIX_X4(al[mf][0], al[mf][1], al[mf][2], al[mf][3], ad + A_AGL);
            }
            uint32_t kbh[4][2], kbl[4][2];
#pragma unroll
            for (int p = 0; p < 2; ++p) {
                uint32_t ad = KH + (p * 16 + b_row) * A_STR + kf * 32 + b_kb;
                LDMATRIX_X4(kbh[p * 2][0], kbh[p * 2][1], kbh[p * 2 + 1][0], kbh[p * 2 + 1][1], ad);
                uint32_t ad2 = KL + (p * 16 + b_row) * A_STR + kf * 32 + b_kb;
                LDMATRIX_X4(kbl[p * 2][0], kbl[p * 2][1], kbl[p * 2 + 1][0], kbl[p * 2 + 1][1], ad2);
            }
#pragma unroll
            for (int mf = 0; mf < 2; ++mf)
#pragma unroll
                for (int nf = 0; nf < 4; ++nf) {
                    MMA_BF16(s[mf][nf], ah[mf], kbh[nf]);
                    MMA_BF16(s[mf][nf], ah[mf], kbl[nf]);
                    MMA_BF16(s[mf][nf], al[mf], kbh[nf]);
                }
        }

        uint32_t ph[2][2][4], pl[2][2][4];
#pragma unroll
        for (int mf = 0; mf < 2; ++mf) {
#pragma unroll
            for (int nf = 0; nf < 4; ++nf) {
                s[mf][nf][0] = __expf(s[mf][nf][0]);
                s[mf][nf][1] = __expf(s[mf][nf][1]);
                s[mf][nf][2] = __expf(s[mf][nf][2]);
                s[mf][nf][3] = __expf(s[mf][nf][3]);
                rs[mf][0] += s[mf][nf][0] + s[mf][nf][1];
                rs[mf][1] += s[mf][nf][2] + s[mf][nf][3];
            }
#pragma unroll
            for (int kt = 0; kt < 2; ++kt) {
                split2(s[mf][2 * kt][0],     s[mf][2 * kt][1],     ph[mf][kt][0], pl[mf][kt][0]);
                split2(s[mf][2 * kt][2],     s[mf][2 * kt][3],     ph[mf][kt][1], pl[mf][kt][1]);
                split2(s[mf][2 * kt + 1][0], s[mf][2 * kt + 1][1], ph[mf][kt][2], pl[mf][kt][2]);
                split2(s[mf][2 * kt + 1][2], s[mf][2 * kt + 1][3], ph[mf][kt][3], pl[mf][kt][3]);
            }
        }

#pragma unroll
        for (int kt = 0; kt < 2; ++kt) {
#pragma unroll
            for (int p = 0; p < 4; ++p) {
                uint32_t bvh[2][2], bvl[2][2];
                uint32_t ad = VH + (kt * 16 + v_row) * A_STR + p * 32 + v_cb;
                LDMATRIX_X4_T(bvh[0][0], bvh[0][1], bvh[1][0], bvh[1][1], ad);
                uint32_t ad2 = VL + (kt * 16 + v_row) * A_STR + p * 32 + v_cb;
                LDMATRIX_X4_T(bvl[0][0], bvl[0][1], bvl[1][0], bvl[1][1], ad2);
#pragma unroll
                for (int mf = 0; mf < 2; ++mf)
#pragma unroll
                    for (int j = 0; j < 2; ++j) {
                        int nf = p * 2 + j;
                        MMA_BF16(kvacc[mf][nf], ph[mf][kt], bvh[j]);
                        MMA_BF16(kvacc[mf][nf], ph[mf][kt], bvl[j]);
                        MMA_BF16(kvacc[mf][nf], pl[mf][kt], bvh[j]);
                    }
            }
        }
        __syncthreads();
    }

#pragma unroll
    for (int mf = 0; mf < 2; ++mf)
#pragma unroll
        for (int j = 0; j < 2; ++j) {
            float r = rs[mf][j];
            r += __shfl_xor_sync(0xffffffffu, r, 1);
            r += __shfl_xor_sync(0xffffffffu, r, 2);
            if ((lane & 3) == 0)
                atomicAdd(&ksum[bh * 256 + wid * 32 + mf * 16 + j * 8 + (lane >> 2)], r);
        }
    float* kvb = kv + bh * 16384;
#pragma unroll
    for (int mf = 0; mf < 2; ++mf)
#pragma unroll
        for (int nf = 0; nf < 8; ++nf) {
            int r0 = wid * 32 + mf * 16 + (lane >> 2);
            int c  = nf * 8 + (lane & 3) * 2;
            atomicAdd(&kvb[r0 * 64 + c],           kvacc[mf][nf][0]);
            atomicAdd(&kvb[r0 * 64 + c + 1],       kvacc[mf][nf][1]);
            atomicAdd(&kvb[(r0 + 8) * 64 + c],     kvacc[mf][nf][2]);
            atomicAdd(&kvb[(r0 + 8) * 64 + c + 1], kvacc[mf][nf][3]);
        }
}

// kv /= ksum
__global__ __launch_bounds__(256)
void kv_div_kernel(float* __restrict__ kv, const float* __restrict__ ksum) {
    int i = blockIdx.x * 256 + threadIdx.x;
    kv[i] = kv[i] / ksum[i >> 6];
}

// thresh: tsum = sum_i kv_flat[i] * w_thresh[i % 512]
__global__ __launch_bounds__(256)
void thresh_kernel(const float* __restrict__ kv, const float* __restrict__ wth)
{
    __shared__ float red[256];
    float s = 0.f;
    for (long i = blockIdx.x * 256 + threadIdx.x; i < 16L * 256 * 64;
         i += (long)gridDim.x * 256) {
        s += kv[i] * wth[i & 511];
    }
    red[threadIdx.x] = s; __syncthreads();
    for (int st = 128; st > 0; st >>= 1) {
        if (threadIdx.x < st) red[threadIdx.x] += red[threadIdx.x + st];
        __syncthreads();
    }
    if (threadIdx.x == 0) atomicAdd(&g_tsum, red[0]);
}

__device__ __forceinline__ float sigmoidf_(float x) { return 1.f / (1.f + expf(-x)); }

// ===========================================================================
// kv2 = softmax_d(kv*mask + denoise); write TRANSPOSED bf16 hi/lo [bh][d][a]
// ===========================================================================
__global__ __launch_bounds__(64)
void kv2_kernel(const float* __restrict__ kv,
                __nv_bfloat16* __restrict__ kth, __nv_bfloat16* __restrict__ ktl,
                const float* __restrict__ wn, const float* __restrict__ bn,
                const float* __restrict__ wm, const float* __restrict__ bm,
                const float* __restrict__ bth)
{
    long r = blockIdx.x;
    int bh = (int)(r >> 8), a = (int)(r & 255);
    int d = threadIdx.x;
    __shared__ float kr[64];
    __shared__ float tmp[64];

    kr[d] = kv[r * 64 + d];
    __syncthreads();

    float thresh = sigmoidf_(g_tsum * (1.f / 512.f) + bth[0]);

    float sn = bn[d], sm = bm[d];
#pragma unroll 8
    for (int e = 0; e < 64; e++) {
        float ke = kr[e];
        sn += ke * wn[d * 64 + e];
        sm += ke * wm[d * 64 + e];
    }
    float denoise = sigmoidf_(sn);
    float mval    = sigmoidf_(sm);
    float mbin    = (mval > thresh) ? 1.f : 0.f;
    float val     = kr[d] * mbin + denoise;

    tmp[d] = val; __syncthreads();
    float mx = -3.4e38f;
    for (int e = 0; e < 64; e++) mx = fmaxf(mx, tmp[e]);
    __syncthreads();
    float ev = expf(val - mx);
    tmp[d] = ev; __syncthreads();
    float sum = 0.f;
    for (int e = 0; e < 64; e++) sum += tmp[e];
    float v = ev / sum;
    __nv_bfloat16 hh = __float2bfloat16_rn(v);
    kth[bh * 16384 + d * 256 + a] = hh;
    ktl[bh * 16384 + d * 256 + a] = __float2bfloat16_rn(v - __bfloat162float(hh));
}

// ===========================================================================
// Fused stage B: L = q@agent^T (q pre-scaled), P = exp, O = P@kv2t, /rowsum.
// qtile 128, 8 warps x 16 rows (row-exclusive, no cross-warp reduction).
// grid (64, 16), 256 threads.
// ===========================================================================
static constexpr int O_QL   = 18432;
static constexpr int O_AG   = 36864;   // agent hi base
static constexpr int O_AGL  = 36864;   // lo offset relative to O_AG
static constexpr int O_KT   = 110592;  // kv2t hi base
static constexpr int O_KTL  = 33792;   // lo offset relative to O_KT
static constexpr int O_SMEM = 178176;
static constexpr int KT_STR = 528;

__global__ __launch_bounds__(256)
void attn_out_kernel(const __nv_bfloat16* __restrict__ qh,
                     const __nv_bfloat16* __restrict__ ql,
                     const __nv_bfloat16* __restrict__ agh,
                     const __nv_bfloat16* __restrict__ agl,
                     const __nv_bfloat16* __restrict__ kth,
                     const __nv_bfloat16* __restrict__ ktl,
                     float* __restrict__ out)
{
    extern __shared__ char smem[];
    uint32_t sb = smem_to_u32(smem);
    int tid = threadIdx.x, lane = tid & 31, wid = tid >> 5;
    int qt = blockIdx.x, bh = blockIdx.y;
    int b = bh >> 3, h = bh & 7;
    int wr = wid * 16;
    int t8 = lane >> 3, rin = lane & 7;
    int a_row = rin + (t8 & 1) * 8, a_kb = (t8 >> 1) * 16;
    int b_row = (t8 >> 1) * 8 + rin, b_kb = (t8 & 1) * 16;

    // ---- prologue loads (all cp.async)
    {
        long qbase = (long)bh * 8192 * 64 + (long)(qt * 128) * 64;
        for (int i = tid; i < 1024; i += 256) {
            int r = i >> 3, c = i & 7;
            CP_ASYNC16(sb + r * 144 + c * 16,        qh + qbase + r * 64 + c * 8);
            CP_ASYNC16(sb + O_QL + r * 144 + c * 16, ql + qbase + r * 64 + c * 8);
        }
        const __nv_bfloat16* ah_p = agh + h * 16384;
        const __nv_bfloat16* al_p = agl + h * 16384;
        for (int i = tid; i < 2048; i += 256) {
            int r = i >> 3, c = i & 7;
            CP_ASYNC16(sb + O_AG + r * 144 + c * 16,         ah_p + r * 64 + c * 8);
            CP_ASYNC16(sb + O_AG + O_AGL + r * 144 + c * 16, al_p + r * 64 + c * 8);
        }
        for (int i = tid; i < 2048; i += 256) {
            int r = i >> 5, c = i & 31;
            CP_ASYNC16(sb + O_KT + r * KT_STR + c * 16,         kth + bh * 16384 + r * 256 + c * 8);
            CP_ASYNC16(sb + O_KT + O_KTL + r * KT_STR + c * 16, ktl + bh * 16384 + r * 256 + c * 8);
        }
        CP_COMMIT(); CP_WAIT0();
        __syncthreads();
    }

    // ---- S = Q @ agent^T : per warp 16 rows x 256 agents
    float s[32][4];
#pragma unroll
    for (int i = 0; i < 32; i++)
#pragma unroll
        for (int q = 0; q < 4; q++) s[i][q] = 0.f;

#pragma unroll
    for (int kf = 0; kf < 4; ++kf) {
        uint32_t ah[4], al[4];
        uint32_t ad = sb + (wr + a_row) * 144 + kf * 32 + a_kb;
        LDMATRIX_X4(ah[0], ah[1], ah[2], ah[3], ad);
        LDMATRIX_X4(al[0], al[1], al[2], al[3], ad + O_QL);
#pragma unroll
        for (int p = 0; p < 16; ++p) {
            uint32_t bhf[2][2], blf[2][2];
            uint32_t bd = sb + O_AG + (p * 16 + b_row) * 144 + kf * 32 + b_kb;
            LDMATRIX_X4(bhf[0][0], bhf[0][1], bhf[1][0], bhf[1][1], bd);
            LDMATRIX_X4(blf[0][0], blf[0][1], blf[1][0], blf[1][1], bd + O_AGL);
#pragma unroll
            for (int j = 0; j < 2; ++j) {
                int nf = p * 2 + j;
                MMA_BF16(s[nf], ah, bhf[j]);
                MMA_BF16(s[nf], ah, blf[j]);
                MMA_BF16(s[nf], al, bhf[j]);
            }
        }
    }

    // ---- exp + rowsums (rows exclusive to this warp)
    float rs0 = 0.f, rs1 = 0.f;
#pragma unroll
    for (int nf = 0; nf < 32; ++nf) {
        s[nf][0] = __expf(s[nf][0]);
        s[nf][1] = __expf(s[nf][1]);
        s[nf][2] = __expf(s[nf][2]);
        s[nf][3] = __expf(s[nf][3]);
        rs0 += s[nf][0] + s[nf][1];
        rs1 += s[nf][2] + s[nf][3];
    }
    rs0 += __shfl_xor_sync(0xffffffffu, rs0, 1);
    rs0 += __shfl_xor_sync(0xffffffffu, rs0, 2);
    rs1 += __shfl_xor_sync(0xffffffffu, rs1, 1);
    rs1 += __shfl_xor_sync(0xffffffffu, rs1, 2);
    float inv0 = 1.f / rs0, inv1 = 1.f / rs1;

    // ---- pack P frags (A-operand layout)
    uint32_t ph[16][4], pl[16][4];
#pragma unroll
    for (int kt = 0; kt < 16; ++kt) {
        split2(s[2 * kt][0],     s[2 * kt][1],     ph[kt][0], pl[kt][0]);
        split2(s[2 * kt][2],     s[2 * kt][3],     ph[kt][1], pl[kt][1]);
        split2(s[2 * kt + 1][0], s[2 * kt + 1][1], ph[kt][2], pl[kt][2]);
        split2(s[2 * kt + 1][2], s[2 * kt + 1][3], ph[kt][3], pl[kt][3]);
    }

    // ---- O = P @ kv2t : 16 rows x 64 d, k = 256 agents
    float o[8][4];
#pragma unroll
    for (int i = 0; i < 8; i++)
#pragma unroll
        for (int q = 0; q < 4; q++) o[i][q] = 0.f;

#pragma unroll
    for (int kt = 0; kt < 16; ++kt) {
#pragma unroll
        for (int p = 0; p < 4; ++p) {
            uint32_t bhf[2][2], blf[2][2];
            uint32_t bd = sb + O_KT + (p * 16 + b_row) * KT_STR + kt * 32 + b_kb;
            LDMATRIX_X4(bhf[0][0], bhf[0][1], bhf[1][0], bhf[1][1], bd);
            LDMATRIX_X4(blf[0][0], blf[0][1], blf[1][0], blf[1][1], bd + O_KTL);
#pragma unroll
            for (int j = 0; j < 2; ++j) {
                int nf = p * 2 + j;
                MMA_BF16(o[nf], ph[kt], bhf[j]);
                MMA_BF16(o[nf], ph[kt], blf[j]);
                MMA_BF16(o[nf], pl[kt], bhf[j]);
            }
        }
    }

    // ---- write out with per-row normalization
    int r0 = qt * 128 + wr + (lane >> 2);
#pragma unroll
    for (int nf = 0; nf < 8; ++nf) {
        int c = nf * 8 + (lane & 3) * 2;
        long gr = ((long)(b * 8192 + r0)) * 512 + h * 64 + c;
        *(float2*)(out + gr)           = make_float2(o[nf][0] * inv0, o[nf][1] * inv0);
        *(float2*)(out + gr + 8 * 512) = make_float2(o[nf][2] * inv1, o[nf][3] * inv1);
    }
}

// ===========================================================================
extern "C" void kernel_launch(void* const* d_in, const int* in_sizes, int n_in,
                              void* d_out, int out_size)
{
    const float* x        = (const float*)d_in[0];
    const float* w_qkv    = (const float*)d_in[1];
    const float* agent    = (const float*)d_in[2];
    const float* w_noise  = (const float*)d_in[3];
    const float* b_noise  = (const float*)d_in[4];
    const float* w_mask   = (const float*)d_in[5];
    const float* b_mask   = (const float*)d_in[6];
    const float* w_thresh = (const float*)d_in[7];
    const float* b_thresh = (const float*)d_in[8];
    float* out = (float*)d_out;

    float *kv, *ksum;
    __nv_bfloat16 *xh, *xl, *wh, *wl, *agh, *agl, *kth, *ktl;
    __nv_bfloat16 *qh, *ql, *kh, *kl, *vh, *vl;
    cudaGetSymbolAddress((void**)&kv,  g_kv);
    cudaGetSymbolAddress((void**)&ksum, g_ksum);
    cudaGetSymbolAddress((void**)&xh,  g_xh);
    cudaGetSymbolAddress((void**)&xl,  g_xl);
    cudaGetSymbolAddress((void**)&wh,  g_wh);
    cudaGetSymbolAddress((void**)&wl,  g_wl);
    cudaGetSymbolAddress((void**)&agh, g_agh);
    cudaGetSymbolAddress((void**)&agl, g_agl);
    cudaGetSymbolAddress((void**)&kth, g_kt_h);
    cudaGetSymbolAddress((void**)&ktl, g_kt_l);
    cudaGetSymbolAddress((void**)&qh,  g_qh);
    cudaGetSymbolAddress((void**)&ql,  g_ql);
    cudaGetSymbolAddress((void**)&kh,  g_kh);
    cudaGetSymbolAddress((void**)&kl,  g_kl);
    cudaGetSymbolAddress((void**)&vh,  g_vh);
    cudaGetSymbolAddress((void**)&vl,  g_vl);

    cudaFuncSetAttribute(k1_mma_kernel,
                         cudaFuncAttributeMaxDynamicSharedMemorySize, K1_SMEM);
    cudaFuncSetAttribute(attn_kv_kernel,
                         cudaFuncAttributeMaxDynamicSharedMemorySize, A_SMEM);
    cudaFuncSetAttribute(attn_out_kernel,
                         cudaFuncAttributeMaxDynamicSharedMemorySize, O_SMEM);

    init_kernel<<<256, 256>>>();

    // 0) bf16 hi/lo splits of inputs
    split_bf16<<<1024, 256>>>(x, xh, xl, 16384L * 512);
    split_bf16<<<256, 256>>>(w_qkv, wh, wl, 1536L * 512);
    split_bf16<<<128, 256>>>(agent, agh, agl, 8L * 256 * 64);

    // 1) qkv GEMM; epilogue writes q/k/v presplit head-major (q scaled 1/8)
    k1_mma_kernel<<<dim3(12, 128), 256, K1_SMEM>>>(xh, xl, wh, wl,
                                                   qh, ql, kh, kl, vh, vl);

    // 2) fused: ka softmax-partials + kv accumulation
    attn_kv_kernel<<<dim3(16, 16), 256, A_SMEM>>>(kh, kl, vh, vl, agh, agl, kv, ksum);

    // 3) normalize kv
    kv_div_kernel<<<1024, 256>>>(kv, ksum);

    // 4) threshold scalar
    thresh_kernel<<<512, 256>>>(kv, w_thresh);

    // 5) mask/denoise + second softmax -> kv2 transposed bf16 hi/lo
    kv2_kernel<<<4096, 64>>>(kv, kth, ktl, w_noise, b_noise, w_mask, b_mask, b_thresh);

    // 6) fused: qa softmax + out = qa @ kv2
    attn_out_kernel<<<dim3(64, 16), 256, O_SMEM>>>(qh, ql, agh, agl, kth, ktl, out);
}